// round 2
// baseline (speedup 1.0000x reference)
#include <cuda_runtime.h>
#include <math.h>

// ---------------------------------------------------------------------------
// Problem constants
// ---------------------------------------------------------------------------
#define HH 192
#define WW 192
#define HW (192*192)
#define BB 4
#define DD 8
#define ICT 40          // conv input channels (always 40 = NF + 8)
#define TILE 32

// ---------------------------------------------------------------------------
// Scratch (device globals — no allocation allowed)
// ---------------------------------------------------------------------------
__device__ float g_h   [BB*8 *HW];   // h state
__device__ float g_c   [BB*8 *HW];   // c state
__device__ float g_r   [BB*40*HW];   // r = [cs, sigmoid(q)]
__device__ float g_gate[BB*56*HW];   // raw gate conv output
__device__ float g_x0  [BB*40*HW];   // raw conv0 output
__device__ float g_x1  [BB*40*HW];   // raw conv1 output
__device__ float g_Wg  [56*40*3*3];  // packed gate weights [oc][ic][ky][kx]
__device__ float g_bg  [56];
__device__ float g_Wh2 [11*40*5*5];  // packed head weights (Wh padded to 5x5 | W2)
__device__ float g_bh2 [11];
__device__ float g_sc0[40], g_sh0[40], g_sc1[40], g_sh1[40];  // BN scale/shift

__device__ __forceinline__ float sigmoidf_(float x) { return 1.f / (1.f + expf(-x)); }

// ---------------------------------------------------------------------------
// Zero the recurrent state
// ---------------------------------------------------------------------------
__global__ void zero_state_kernel() {
    int i = blockIdx.x * blockDim.x + threadIdx.x;
    if (i < BB*8*HW) { g_h[i] = 0.f; g_c[i] = 0.f; }
}

// ---------------------------------------------------------------------------
// Pack weights: gates (Wf|Wi|Wc|Wq -> 56 oc) and head (Wh centered in 5x5 | W2)
// ---------------------------------------------------------------------------
__global__ void prep_weights_kernel(
    const float* __restrict__ Wf, const float* __restrict__ bf,
    const float* __restrict__ Wi, const float* __restrict__ bi,
    const float* __restrict__ Wc, const float* __restrict__ bc,
    const float* __restrict__ Wq, const float* __restrict__ bq,
    const float* __restrict__ Wh, const float* __restrict__ bh,
    const float* __restrict__ W2, const float* __restrict__ b2)
{
    int i = blockIdx.x * blockDim.x + threadIdx.x;
    const int NG = 56*40*9;
    if (i < NG) {
        int oc = i / 360, r = i % 360;
        float v;
        if      (oc < 8 ) v = Wf[ oc     *360 + r];
        else if (oc < 16) v = Wi[(oc-8 ) *360 + r];
        else if (oc < 24) v = Wc[(oc-16) *360 + r];
        else              v = Wq[(oc-24) *360 + r];
        g_Wg[i] = v;
    }
    if (i < 56) {
        g_bg[i] = (i < 8) ? bf[i] : (i < 16) ? bi[i-8] : (i < 24) ? bc[i-16] : bq[i-24];
    }
    const int NH = 11*40*25;
    if (i < NH) {
        int oc = i / 1000, r = i % 1000, c = r / 25, k = r % 25, ky = k / 5, kx = k % 5;
        float v = 0.f;
        if (oc < 8) {
            if (ky >= 1 && ky <= 3 && kx >= 1 && kx <= 3)
                v = Wh[((oc*40 + c)*3 + (ky-1))*3 + (kx-1)];
        } else {
            v = W2[(((oc-8)*40 + c)*5 + ky)*5 + kx];
        }
        g_Wh2[i] = v;
    }
    if (i < 11) g_bh2[i] = (i < 8) ? bh[i] : b2[i-8];
}

// ---------------------------------------------------------------------------
// Generic direct conv.
//  K      : kernel size (3 or 5), pad = K/2
//  OCT    : total output channels
//  MODE   : 0 = store raw to out (B,OCT,H,W)
//           1 = head: oc<8 -> out (h state, B,8,H,W); oc in [8,11) -> out_o
//               at ((b*3+(oc-8))*DD + t)*HW + pix
//  Input: channels [0,c_split) from in1 (batch stride bs1),
//         channels [c_split,40) from in2 (batch stride bs2).
//  Optional per-channel input transform:  v = max(v*isc[c]+ish[c], 0)  (BN+ReLU)
//  Tiling: 32x32 output pixels, 8 oc per block, 256 threads,
//          each thread: 4 pixels (y strided by 8) x 8 oc register tile.
// ---------------------------------------------------------------------------
template<int K, int OCT, int MODE>
__global__ __launch_bounds__(256, 2)
void conv_kernel(
    const float* __restrict__ in1, long bs1,
    const float* __restrict__ in2, long bs2, int c_split,
    const float* __restrict__ Wt,  const float* __restrict__ bias,
    const float* __restrict__ isc, const float* __restrict__ ish,
    float* __restrict__ out, float* __restrict__ out_o, int t)
{
    constexpr int PS  = TILE + K - 1;
    constexpr int PAD = K / 2;
    constexpr int NGROUP = (OCT + 7) / 8;

    __shared__ __align__(16) float patch[8 * PS * PS];
    __shared__ __align__(16) float wts  [8 * K * K * 8];

    const int b   = blockIdx.z / NGROUP;
    const int g   = blockIdx.z % NGROUP;
    const int tx0 = blockIdx.x * TILE;
    const int ty0 = blockIdx.y * TILE;
    const int tid = threadIdx.x;
    const int x   = tid & 31;
    const int y0  = tid >> 5;          // 0..7

    float acc[4][8];
    #pragma unroll
    for (int o = 0; o < 8; ++o) {
        int oc = g*8 + o;
        float bini = (bias != nullptr && oc < OCT) ? __ldg(&bias[oc]) : 0.f;
        #pragma unroll
        for (int p = 0; p < 4; ++p) acc[p][o] = bini;
    }

    for (int chunk = 0; chunk < 5; ++chunk) {
        __syncthreads();
        // ---- load input patch (8 channels) ----
        for (int idx = tid; idx < 8*PS*PS; idx += 256) {
            int c  = idx / (PS*PS);
            int r  = idx - c*PS*PS;
            int yy = r / PS, xx = r - yy*PS;
            int gy = ty0 + yy - PAD, gx = tx0 + xx - PAD;
            float v = 0.f;
            if ((unsigned)gy < HH && (unsigned)gx < WW) {
                int cg = chunk*8 + c;
                const float* src; int cc;
                if (cg < c_split) { src = in1 + (long)b*bs1; cc = cg; }
                else              { src = in2 + (long)b*bs2; cc = cg - c_split; }
                v = __ldg(src + (long)cc*HW + gy*WW + gx);
                if (isc != nullptr) v = fmaxf(v * isc[cg] + ish[cg], 0.f);
            }
            patch[idx] = v;
        }
        // ---- load weight chunk: layout ((c*K+ky)*K+kx)*8 + oc ----
        for (int idx = tid; idx < 8*K*K*8; idx += 256) {
            int oc   = idx & 7;
            int rest = idx >> 3;
            int kx = rest % K; rest /= K;
            int ky = rest % K;
            int c  = rest / K;
            int ocg = g*8 + oc;
            float wv = 0.f;
            if (ocg < OCT)
                wv = __ldg(&Wt[((long)ocg*ICT + chunk*8 + c)*K*K + ky*K + kx]);
            wts[idx] = wv;
        }
        __syncthreads();
        // ---- compute ----
        #pragma unroll 1
        for (int c = 0; c < 8; ++c) {
            const float* pc_ = &patch[c*PS*PS];
            #pragma unroll
            for (int ky = 0; ky < K; ++ky) {
                #pragma unroll
                for (int kx = 0; kx < K; ++kx) {
                    const float* wp = &wts[((c*K + ky)*K + kx)*8];
                    float w8[8];
                    *(float4*)&w8[0] = *(const float4*)wp;
                    *(float4*)&w8[4] = *(const float4*)(wp + 4);
                    float iv[4];
                    #pragma unroll
                    for (int p = 0; p < 4; ++p)
                        iv[p] = pc_[(y0 + p*8 + ky)*PS + x + kx];
                    #pragma unroll
                    for (int p = 0; p < 4; ++p)
                        #pragma unroll
                        for (int o = 0; o < 8; ++o)
                            acc[p][o] = fmaf(iv[p], w8[o], acc[p][o]);
                }
            }
        }
    }

    // ---- store ----
    #pragma unroll
    for (int p = 0; p < 4; ++p) {
        int y   = ty0 + y0 + p*8;
        int pix = y*WW + tx0 + x;
        #pragma unroll
        for (int o = 0; o < 8; ++o) {
            int oc = g*8 + o;
            if (oc >= OCT) continue;
            float v = acc[p][o];
            if (MODE == 0) {
                out[((long)b*OCT + oc)*HW + pix] = v;
            } else {
                if (oc < 8) out[((long)b*8 + oc)*HW + pix] = v;
                else        out_o[(((long)b*3 + (oc-8))*DD + t)*HW + pix] = v;
            }
        }
    }
}

// ---------------------------------------------------------------------------
// LSTM pointwise update:
//  f,i,g,q from raw gates; c' = sig(f)*c + sig(i)*tanh(g);
//  r[0:8]=c', r[8:40]=sig(q)
// ---------------------------------------------------------------------------
__global__ void lstm_update_kernel(const float* __restrict__ gates,
                                   float* __restrict__ cbuf,
                                   float* __restrict__ rbuf)
{
    int i = blockIdx.x * blockDim.x + threadIdx.x;
    if (i >= BB*HW) return;
    int b = i / HW, p = i - b*HW;
    const float* G = gates + (long)b*56*HW + p;
    float*       C = cbuf  + (long)b*8 *HW + p;
    float*       R = rbuf  + (long)b*40*HW + p;
    #pragma unroll
    for (int c = 0; c < 8; ++c) {
        float f  = sigmoidf_(G[(c     )*HW]);
        float ii = sigmoidf_(G[(c + 8 )*HW]);
        float gg = tanhf    (G[(c + 16)*HW]);
        float cs = f * C[c*HW] + ii * gg;
        C[c*HW] = cs;
        R[c*HW] = cs;
    }
    #pragma unroll
    for (int c = 0; c < 32; ++c)
        R[(8 + c)*HW] = sigmoidf_(G[(24 + c)*HW]);
}

// ---------------------------------------------------------------------------
// Deterministic training-mode BN stats: one block per channel.
// Produces scale = gamma*rsqrt(var+eps), shift = beta - mean*scale.
// ---------------------------------------------------------------------------
__global__ void bn_stats_kernel(const float* __restrict__ x,
                                const float* __restrict__ gamma,
                                const float* __restrict__ beta,
                                float* __restrict__ scale,
                                float* __restrict__ shift)
{
    const int c = blockIdx.x;
    float s = 0.f, q = 0.f;
    for (int b = 0; b < BB; ++b) {
        const float4* p = (const float4*)(x + ((long)b*40 + c)*HW);
        for (int i = threadIdx.x; i < HW/4; i += blockDim.x) {
            float4 v = __ldg(&p[i]);
            s += v.x + v.y + v.z + v.w;
            q += v.x*v.x + v.y*v.y + v.z*v.z + v.w*v.w;
        }
    }
    __shared__ float ss[32], sq[32];
    #pragma unroll
    for (int o = 16; o; o >>= 1) {
        s += __shfl_xor_sync(~0u, s, o);
        q += __shfl_xor_sync(~0u, q, o);
    }
    int lane = threadIdx.x & 31, w = threadIdx.x >> 5;
    if (!lane) { ss[w] = s; sq[w] = q; }
    __syncthreads();
    if (threadIdx.x < 32) {
        int nw = blockDim.x >> 5;
        s = (threadIdx.x < nw) ? ss[threadIdx.x] : 0.f;
        q = (threadIdx.x < nw) ? sq[threadIdx.x] : 0.f;
        #pragma unroll
        for (int o = 16; o; o >>= 1) {
            s += __shfl_xor_sync(~0u, s, o);
            q += __shfl_xor_sync(~0u, q, o);
        }
        if (threadIdx.x == 0) {
            const float N = (float)(BB*HW);
            float m  = s / N;
            float v  = q / N - m*m;
            float sc = gamma[c] * rsqrtf(v + 1e-5f);
            scale[c] = sc;
            shift[c] = beta[c] - m*sc;
        }
    }
}

// ---------------------------------------------------------------------------
// Host driver
// ---------------------------------------------------------------------------
extern "C" void kernel_launch(void* const* d_in, const int* in_sizes, int n_in,
                              void* d_out, int out_size)
{
    const float* x1  = (const float*)d_in[0];
    const float* x2  = (const float*)d_in[1];
    const float* Wf  = (const float*)d_in[2];
    const float* bf  = (const float*)d_in[3];
    const float* Wi  = (const float*)d_in[4];
    const float* bi  = (const float*)d_in[5];
    const float* Wc  = (const float*)d_in[6];
    const float* bc  = (const float*)d_in[7];
    const float* Wq  = (const float*)d_in[8];
    const float* bq  = (const float*)d_in[9];
    const float* W0  = (const float*)d_in[10];
    const float* g0  = (const float*)d_in[11];
    const float* be0 = (const float*)d_in[12];
    const float* W1  = (const float*)d_in[13];
    const float* g1  = (const float*)d_in[14];
    const float* be1 = (const float*)d_in[15];
    const float* W2  = (const float*)d_in[16];
    const float* b2w = (const float*)d_in[17];
    const float* Wh  = (const float*)d_in[18];
    const float* bh  = (const float*)d_in[19];
    float* out = (float*)d_out;

    float *ph, *pc, *pr, *pg, *px0, *px1, *pWg, *pbg, *pWh2, *pbh2;
    float *psc0, *psh0, *psc1, *psh1;
    cudaGetSymbolAddress((void**)&ph,   g_h);
    cudaGetSymbolAddress((void**)&pc,   g_c);
    cudaGetSymbolAddress((void**)&pr,   g_r);
    cudaGetSymbolAddress((void**)&pg,   g_gate);
    cudaGetSymbolAddress((void**)&px0,  g_x0);
    cudaGetSymbolAddress((void**)&px1,  g_x1);
    cudaGetSymbolAddress((void**)&pWg,  g_Wg);
    cudaGetSymbolAddress((void**)&pbg,  g_bg);
    cudaGetSymbolAddress((void**)&pWh2, g_Wh2);
    cudaGetSymbolAddress((void**)&pbh2, g_bh2);
    cudaGetSymbolAddress((void**)&psc0, g_sc0);
    cudaGetSymbolAddress((void**)&psh0, g_sh0);
    cudaGetSymbolAddress((void**)&psc1, g_sc1);
    cudaGetSymbolAddress((void**)&psh1, g_sh1);

    zero_state_kernel<<<(BB*8*HW + 255)/256, 256>>>();
    prep_weights_kernel<<<(56*40*9 + 255)/256, 256>>>(Wf, bf, Wi, bi, Wc, bc, Wq, bq,
                                                      Wh, bh, W2, b2w);

    const long O2_OFF = (long)BB*3*DD*HW;   // o1 tensor size

    for (int t = 0; t < DD; ++t) {
        for (int phase = 0; phase < 2; ++phase) {
            const float* xin   = (phase ? x2 : x1) + (long)t*32*HW;
            float*       obase = out + (phase ? O2_OFF : 0);

            // gate conv: concat(x[32], h[8]) -> 56 raw gates
            conv_kernel<3, 56, 0><<<dim3(6, 6, BB*7), 256>>>(
                xin, (long)DD*32*HW, ph, (long)8*HW, 32,
                pWg, pbg, nullptr, nullptr, pg, nullptr, 0);

            // LSTM pointwise: update c, build r = [c', sig(q)]
            lstm_update_kernel<<<(BB*HW + 255)/256, 256>>>(pg, pc, pr);

            // conv0: 5x5 r -> raw x0
            conv_kernel<5, 40, 0><<<dim3(6, 6, BB*5), 256>>>(
                pr, (long)40*HW, nullptr, 0, 40,
                W0, nullptr, nullptr, nullptr, px0, nullptr, 0);
            bn_stats_kernel<<<40, 512>>>(px0, g0, be0, psc0, psh0);

            // conv1: 5x5 relu(bn0(x0)) -> raw x1
            conv_kernel<5, 40, 0><<<dim3(6, 6, BB*5), 256>>>(
                px0, (long)40*HW, nullptr, 0, 40,
                W1, nullptr, psc0, psh0, px1, nullptr, 0);
            bn_stats_kernel<<<40, 512>>>(px1, g1, be1, psc1, psh1);

            // head: 5x5 relu(bn1(x1)) -> h (oc 0-7) + depth out (oc 8-10)
            conv_kernel<5, 11, 1><<<dim3(6, 6, BB*2), 256>>>(
                px1, (long)40*HW, nullptr, 0, 40,
                pWh2, pbh2, psc1, psh1, ph, obase, t);
        }
    }
}